// round 4
// baseline (speedup 1.0000x reference)
#include <cuda_runtime.h>
#include <cuda_bf16.h>

// HGNN forward, fully fused. One block per graph (B=256 blocks, 512 threads).
//   M[e,d]  = (1/32) * sum_{v in graph} H[v,e] * x[v,d]
//   s[e]    = sum_{v in graph} H[v,e]
//   ED[e,f] = relu(sum_d M[e,d]*W[f,d] + bias[f])      -> h_e output
//   c[f]    = (1/(32*48)) * sum_e s[e]*ED[e,f]         -> c output
// Output buffer: [ c (B*D) | h_e (B*E*D) ]
//
// R4: 512 threads/block. Occupancy was grid-limited (256 blocks x 8 warps =
// 13.8 warps/SM); doubling warps per block puts the whole grid resident in
// one wave (~27.7 warps/SM). 64-reg budget keeps 2 blocks/SM (full RF).

constexpr int V   = 8192;
constexpr int E   = 48;
constexpr int D   = 64;
constexpr int B   = 256;
constexpr int NPG = V / B;        // 32 nodes per graph
constexpr int NT  = 512;          // threads per block
constexpr int NQ  = NT / D;       // 8 e-quarters
constexpr int EPT = E / NQ;       // 6 e-entries per thread

__global__ __launch_bounds__(NT, 2) void hgnn_fused_kernel(
    const float* __restrict__ x,     // (V, D)
    const float* __restrict__ Hm,    // (V, E)
    const float* __restrict__ W,     // (D, D) row-major [f][d]
    const float* __restrict__ bias,  // (D,)
    float* __restrict__ out)         // [c | h_e]
{
    __shared__ float Ht[E * NPG];    // transposed H: Ht[e*32+v]   (6 KB)
    __shared__ float Ms[E * D];      // (12 KB)
    __shared__ float Sv[E];
    __shared__ float Bs[D];
    __shared__ float Cp[NQ * D];     // (2 KB)

    const int b = blockIdx.x;
    const int t = threadIdx.x;
    const int f = t & 63;            // feature / d index for this thread
    const int q = t >> 6;            // 0..7 — e-slice

    // ---- stage H transposed into shared ----
    {
        const float4* hg = (const float4*)(Hm + (size_t)b * NPG * E);
        #pragma unroll
        for (int i = t; i < NPG * E / 4; i += NT) {
            float4 h = hg[i];
            int base = i * 4;
            int v = base / E;
            int e = base - v * E;
            Ht[(e + 0) * NPG + v] = h.x;
            Ht[(e + 1) * NPG + v] = h.y;
            Ht[(e + 2) * NPG + v] = h.z;
            Ht[(e + 3) * NPG + v] = h.w;
        }
        if (t < D) Bs[t] = bias[t];
    }
    __syncthreads();

    // ---- s[e] = sum_v Ht[e,v] ----
    if (t < E) {
        const float4* hr = (const float4*)&Ht[t * NPG];
        float a0 = 0.f, a1 = 0.f;
        #pragma unroll
        for (int k = 0; k < NPG / 8; k++) {
            float4 h0 = hr[2 * k], h1 = hr[2 * k + 1];
            a0 += h0.x + h0.y + h0.z + h0.w;
            a1 += h1.x + h1.y + h1.z + h1.w;
        }
        Sv[t] = a0 + a1;
    }

    // ---- phase 1: M[e,f] = (1/32) sum_v Ht[e,v]*x[v,f], chunked over v ----
    float macc[EPT];
    #pragma unroll
    for (int j = 0; j < EPT; j++) macc[j] = 0.f;

    #pragma unroll
    for (int vc = 0; vc < 2; vc++) {
        float xr[16];
        const float* xg = x + (size_t)b * NPG * D + (vc * 16) * D + f;
        #pragma unroll
        for (int v = 0; v < 16; v++) xr[v] = xg[v * D];   // coalesced

        #pragma unroll
        for (int j = 0; j < EPT; j++) {
            int e = j * NQ + q;
            const float4* hr = (const float4*)&Ht[e * NPG + vc * 16]; // bcast
            #pragma unroll
            for (int k = 0; k < 4; k++) {
                float4 h = hr[k];
                macc[j] = fmaf(h.x, xr[4 * k + 0], macc[j]);
                macc[j] = fmaf(h.y, xr[4 * k + 1], macc[j]);
                macc[j] = fmaf(h.z, xr[4 * k + 2], macc[j]);
                macc[j] = fmaf(h.w, xr[4 * k + 3], macc[j]);
            }
        }
    }
    #pragma unroll
    for (int j = 0; j < EPT; j++)
        Ms[(j * NQ + q) * D + f] = macc[j] * (1.0f / NPG);
    __syncthreads();

    // ---- phase 2: ED[e,f] = relu(M[e,:].W[f,:] + bias[f]), chunked over d ----
    float acc[EPT];
    const float bf = Bs[f];
    #pragma unroll
    for (int j = 0; j < EPT; j++) acc[j] = bf;

    #pragma unroll
    for (int dc = 0; dc < 4; dc++) {
        float4 wv[4];
        const float4* wr = (const float4*)(W + (size_t)f * D + dc * 16);
        #pragma unroll
        for (int k = 0; k < 4; k++) wv[k] = wr[k];

        #pragma unroll
        for (int j = 0; j < EPT; j++) {
            int e = j * NQ + q;
            const float4* mr = (const float4*)&Ms[e * D + dc * 16];   // bcast
            #pragma unroll
            for (int k = 0; k < 4; k++) {
                float4 m = mr[k];
                acc[j] = fmaf(m.x, wv[k].x, acc[j]);
                acc[j] = fmaf(m.y, wv[k].y, acc[j]);
                acc[j] = fmaf(m.z, wv[k].z, acc[j]);
                acc[j] = fmaf(m.w, wv[k].w, acc[j]);
            }
        }
    }

    // ---- relu, h_e store, c fold ----
    float cacc = 0.f;
    float* he = out + (size_t)B * D + (size_t)b * E * D;
    #pragma unroll
    for (int j = 0; j < EPT; j++) {
        int e = j * NQ + q;
        float r = fmaxf(acc[j], 0.f);
        he[e * D + f] = r;                                // coalesced 128B/warp
        cacc = fmaf(Sv[e], r, cacc);
    }
    Cp[q * D + f] = cacc;
    __syncthreads();

    if (t < D) {
        float c = 0.f;
        #pragma unroll
        for (int k = 0; k < NQ; k++) c += Cp[k * D + t];
        out[b * D + t] = c * (1.0f / (NPG * E));
    }
}

extern "C" void kernel_launch(void* const* d_in, const int* in_sizes, int n_in,
                              void* d_out, int out_size) {
    const float* x    = (const float*)d_in[0];   // (V,D)
    const float* Hm   = (const float*)d_in[1];   // (V,E)
    const float* W    = (const float*)d_in[2];   // (D,D)
    const float* bias = (const float*)d_in[3];   // (D,)
    float* out = (float*)d_out;

    hgnn_fused_kernel<<<B, NT>>>(x, Hm, W, bias, out);
}

// round 5
// speedup vs baseline: 1.4396x; 1.4396x over previous
#include <cuda_runtime.h>
#include <cuda_bf16.h>

// HGNN forward, fully fused. One block per graph (B=256 blocks, 512 threads).
//   M[e,d]  = (1/32) * sum_{v in graph} H[v,e] * x[v,d]
//   s[e]    = sum_{v in graph} H[v,e]
//   ED[e,f] = relu(sum_d M[e,d]*W[f,d] + bias[f])      -> h_e output
//   c[f]    = (1/(32*48)) * sum_e s[e]*ED[e,f]         -> c output
// Output buffer: [ c (B*D) | h_e (B*E*D) ]
//
// R5: W staged into shared, TRANSPOSED + padded (Wt[d*65+f]). The R2-R4
// kernels loaded W rows with 256B-strided LDG.128 -> 32 wavefronts per
// instruction, ~70% of all L1tex work (the measured 55-65% L1 ceiling).
// Conflict-free scalar LDS cuts W wavefronts 8x.

constexpr int V   = 8192;
constexpr int E   = 48;
constexpr int D   = 64;
constexpr int B   = 256;
constexpr int NPG = V / B;        // 32 nodes per graph
constexpr int NT  = 512;          // threads per block
constexpr int NQ  = NT / D;       // 8 e-slices
constexpr int EPT = E / NQ;       // 6 e-entries per thread
constexpr int WP  = D + 1;        // padded W row stride (65)

__global__ __launch_bounds__(NT, 2) void hgnn_fused_kernel(
    const float* __restrict__ x,     // (V, D)
    const float* __restrict__ Hm,    // (V, E)
    const float* __restrict__ W,     // (D, D) row-major [f][d]
    const float* __restrict__ bias,  // (D,)
    float* __restrict__ out)         // [c | h_e]
{
    __shared__ float Ht[E * NPG];     // transposed H: Ht[e*32+v]    (6 KB)
    __shared__ float Wt[D * WP];      // Wt[d*65+f] = W[f*64+d]      (16.25 KB)
    __shared__ float Ms[E * D];       // (12 KB)
    __shared__ float Sv[E];
    __shared__ float Bs[D];
    __shared__ float Cp[NQ * D];      // (2 KB)

    const int b = blockIdx.x;
    const int t = threadIdx.x;
    const int f = t & 63;             // feature / d index for this thread
    const int q = t >> 6;             // 0..7 — e-slice

    // ---- stage H transposed + W transposed(padded) into shared ----
    {
        const float4* hg = (const float4*)(Hm + (size_t)b * NPG * E);
        #pragma unroll
        for (int i = t; i < NPG * E / 4; i += NT) {
            float4 h = hg[i];
            int base = i * 4;
            int v = base / E;
            int e = base - v * E;
            Ht[(e + 0) * NPG + v] = h.x;
            Ht[(e + 1) * NPG + v] = h.y;
            Ht[(e + 2) * NPG + v] = h.z;
            Ht[(e + 3) * NPG + v] = h.w;
        }
        // W: coalesced LDG; STS banks (d+f)%32 -> conflict-free
        #pragma unroll
        for (int i = t; i < D * D; i += NT) {
            int fw = i >> 6, d = i & 63;
            Wt[d * WP + fw] = W[i];
        }
        if (t < D) Bs[t] = bias[t];
    }
    __syncthreads();

    // ---- s[e] = sum_v Ht[e,v] ----
    if (t < E) {
        const float4* hr = (const float4*)&Ht[t * NPG];
        float a0 = 0.f, a1 = 0.f;
        #pragma unroll
        for (int k = 0; k < NPG / 8; k++) {
            float4 h0 = hr[2 * k], h1 = hr[2 * k + 1];
            a0 += h0.x + h0.y + h0.z + h0.w;
            a1 += h1.x + h1.y + h1.z + h1.w;
        }
        Sv[t] = a0 + a1;
    }

    // ---- phase 1: M[e,f] = (1/32) sum_v Ht[e,v]*x[v,f], chunked over v ----
    float macc[EPT];
    #pragma unroll
    for (int j = 0; j < EPT; j++) macc[j] = 0.f;

    #pragma unroll
    for (int vc = 0; vc < 2; vc++) {
        float xr[16];
        const float* xg = x + (size_t)b * NPG * D + (vc * 16) * D + f;
        #pragma unroll
        for (int v = 0; v < 16; v++) xr[v] = xg[v * D];   // coalesced, 1 line/instr

        #pragma unroll
        for (int j = 0; j < EPT; j++) {
            int e = j * NQ + q;
            const float4* hr = (const float4*)&Ht[e * NPG + vc * 16]; // bcast
            #pragma unroll
            for (int k = 0; k < 4; k++) {
                float4 h = hr[k];
                macc[j] = fmaf(h.x, xr[4 * k + 0], macc[j]);
                macc[j] = fmaf(h.y, xr[4 * k + 1], macc[j]);
                macc[j] = fmaf(h.z, xr[4 * k + 2], macc[j]);
                macc[j] = fmaf(h.w, xr[4 * k + 3], macc[j]);
            }
        }
    }
    #pragma unroll
    for (int j = 0; j < EPT; j++)
        Ms[(j * NQ + q) * D + f] = macc[j] * (1.0f / NPG);
    __syncthreads();

    // ---- phase 2: ED[e,f] = relu(M[e,:].W[f,:] + bias[f]), chunked over d ----
    float acc[EPT];
    const float bf = Bs[f];
    #pragma unroll
    for (int j = 0; j < EPT; j++) acc[j] = bf;

    #pragma unroll
    for (int dc = 0; dc < 4; dc++) {
        float wv[16];
        #pragma unroll
        for (int k = 0; k < 16; k++)
            wv[k] = Wt[(dc * 16 + k) * WP + f];           // conflict-free LDS

        #pragma unroll
        for (int j = 0; j < EPT; j++) {
            int e = j * NQ + q;
            const float4* mr = (const float4*)&Ms[e * D + dc * 16];   // bcast
            #pragma unroll
            for (int k = 0; k < 4; k++) {
                float4 m = mr[k];
                acc[j] = fmaf(m.x, wv[4 * k + 0], acc[j]);
                acc[j] = fmaf(m.y, wv[4 * k + 1], acc[j]);
                acc[j] = fmaf(m.z, wv[4 * k + 2], acc[j]);
                acc[j] = fmaf(m.w, wv[4 * k + 3], acc[j]);
            }
        }
    }

    // ---- relu, h_e store, c fold ----
    float cacc = 0.f;
    float* he = out + (size_t)B * D + (size_t)b * E * D;
    #pragma unroll
    for (int j = 0; j < EPT; j++) {
        int e = j * NQ + q;
        float r = fmaxf(acc[j], 0.f);
        he[e * D + f] = r;                                // coalesced 128B/warp
        cacc = fmaf(Sv[e], r, cacc);
    }
    Cp[q * D + f] = cacc;
    __syncthreads();

    if (t < D) {
        float c = 0.f;
        #pragma unroll
        for (int k = 0; k < NQ; k++) c += Cp[k * D + t];
        out[b * D + t] = c * (1.0f / (NPG * E));
    }
}

extern "C" void kernel_launch(void* const* d_in, const int* in_sizes, int n_in,
                              void* d_out, int out_size) {
    const float* x    = (const float*)d_in[0];   // (V,D)
    const float* Hm   = (const float*)d_in[1];   // (V,E)
    const float* W    = (const float*)d_in[2];   // (D,D)
    const float* bias = (const float*)d_in[3];   // (D,)
    float* out = (float*)d_out;

    hgnn_fused_kernel<<<B, NT>>>(x, Hm, W, bias, out);
}